// round 6
// baseline (speedup 1.0000x reference)
#include <cuda_runtime.h>
#include <cstdint>
#include <cstddef>

// ---------------- problem constants ----------------
#define E_NUM 8
#define T_MAX 4096
#define DIN   2048
#define DOUT  2048

// GEMM tiling: CTA 128x256, 8 warps (2 M x 4 N), warp tile 64x64, BK=32
#define BM 128
#define BN 256
#define BK 32
#define STAGES 4
#define KITERS (DIN / BK)     // 64

#define A_STAGE_FLOATS (BM * BK)           // 4096  (16 KB)
#define B_STAGE_FLOATS (BN * BK)           // 8192  (32 KB)
#define STAGE_FLOATS   (A_STAGE_FLOATS + B_STAGE_FLOATS)   // 12288
#define A_STAGE_BYTES  (A_STAGE_FLOATS * 4)                // 16384
#define B_STAGE_BYTES  (B_STAGE_FLOATS * 4)                // 32768
#define STAGE_BYTES    (STAGE_FLOATS * 4)                  // 49152
#define SMEM_DYN_BYTES (STAGES * STAGE_BYTES)              // 196608

// ---------------- device scratch ----------------
// Packed, tf32-rounded, smem-image operands.
// Pair-interleaved layout within a kstage block (rowsz = BM or BN):
//   float index = ((slice*rowsz + row)*4 + ((k&3) ^ sw))*2 + ((k>>2)&1)
//   slice = k>>3, sw = (row>>2)&3      (k local to the 32-k stage)
// One float2 slot holds the MMA k-pair (k=c, k=c+4)  -> LDS.64 fragments.
__device__ float g_Wp[(size_t)E_NUM * DOUT * DIN];
__device__ float g_Xp[(size_t)E_NUM * T_MAX * DIN];
__device__ float g_Y[(size_t)E_NUM * T_MAX * DOUT];
__device__ int   g_cnt[E_NUM];
__device__ int   g_tok[E_NUM * T_MAX];
__device__ int   g_tslot[T_MAX * 2];
__device__ float g_tw[T_MAX * 2];

// ---------------- helpers ----------------
__device__ __forceinline__ uint32_t smem_u32(const void* p) {
    uint32_t a;
    asm("{ .reg .u64 t; cvta.to.shared.u64 t, %1; cvt.u32.u64 %0, t; }"
        : "=r"(a) : "l"(p));
    return a;
}
__device__ __forceinline__ unsigned f2tf32(float f) {
    unsigned u;
    asm("cvt.rna.tf32.f32 %0, %1;" : "=r"(u) : "f"(f));
    return u;
}
__device__ __forceinline__ float4 round4(float4 v) {
    v.x = __uint_as_float(f2tf32(v.x));
    v.y = __uint_as_float(f2tf32(v.y));
    v.z = __uint_as_float(f2tf32(v.z));
    v.w = __uint_as_float(f2tf32(v.w));
    return v;
}
// float index inside one kstage block for element (row, k_local)
__device__ __forceinline__ uint32_t pack_idx(int row, int kl, int rowsz) {
    int slice = kl >> 3;
    int sw    = (row >> 2) & 3;
    return (uint32_t)(((slice * rowsz + row) * 4 + ((kl & 3) ^ sw)) * 2 +
                      ((kl >> 2) & 1));
}

#define MBARRIER_INIT(addr, cnt) \
    asm volatile("mbarrier.init.shared.b64 [%0], %1;" :: "r"(addr), "r"(cnt) : "memory")
#define MBARRIER_EXPECT_TX(addr, tx) \
    asm volatile("mbarrier.arrive.expect_tx.shared.b64 _, [%0], %1;" \
                 :: "r"(addr), "r"(tx) : "memory")
#define MBARRIER_WAIT_PARITY(addr, ph) do {                                   \
    uint32_t _m = (addr); uint32_t _p = (ph); uint32_t _d;                    \
    asm volatile("{\n\t.reg .pred p;\n\t"                                     \
        "mbarrier.try_wait.parity.acquire.cta.shared::cta.b64 p, [%1], %2;\n\t"\
        "selp.b32 %0, 1, 0, p;\n\t}"                                          \
        : "=r"(_d) : "r"(_m), "r"(_p) : "memory");                            \
    if (!_d) {                                                                \
        asm volatile("{\n\t.reg .pred P1;\n\t"                                \
            "WL_%=:\n\t"                                                      \
            "mbarrier.try_wait.parity.acquire.cta.shared::cta.b64 P1, [%0], %1, 0x989680;\n\t" \
            "@P1 bra.uni WD_%=;\n\t"                                          \
            "bra.uni WL_%=;\n\t"                                              \
            "WD_%=:\n\t}" :: "r"(_m), "r"(_p) : "memory");                    \
    }                                                                         \
} while (0)

__device__ __forceinline__ void bulk_ld(uint32_t sdst, const void* gsrc,
                                        uint32_t bytes, uint32_t mbar) {
    asm volatile(
        "cp.async.bulk.shared::cluster.global.mbarrier::complete_tx::bytes "
        "[%0], [%1], %2, [%3];"
        :: "r"(sdst), "l"(gsrc), "r"(bytes), "r"(mbar) : "memory");
}

// ---------------- kernel: zero counters ----------------
__global__ void zero_cnt_kernel() {
    if (threadIdx.x < E_NUM) g_cnt[threadIdx.x] = 0;
}

// ---------------- kernel: router ----------------
__global__ void router_kernel(const float* __restrict__ logits, int T) {
    int t = blockIdx.x * blockDim.x + threadIdx.x;
    if (t >= T) return;
    float l[E_NUM];
#pragma unroll
    for (int e = 0; e < E_NUM; e++) l[e] = logits[t * E_NUM + e];
    int i1 = 0; float v1 = l[0];
#pragma unroll
    for (int e = 1; e < E_NUM; e++)
        if (l[e] > v1) { v1 = l[e]; i1 = e; }
    int i2 = -1; float v2 = -3.4e38f;
#pragma unroll
    for (int e = 0; e < E_NUM; e++)
        if (e != i1 && l[e] > v2) { v2 = l[e]; i2 = e; }
    float w1 = 1.0f / (1.0f + expf(v2 - v1));
    float w2 = 1.0f - w1;
    int p1 = atomicAdd(&g_cnt[i1], 1);
    g_tok[i1 * T_MAX + p1] = t;
    int p2 = atomicAdd(&g_cnt[i2], 1);
    g_tok[i2 * T_MAX + p2] = t;
    g_tslot[2 * t]     = i1 * T_MAX + p1;  g_tw[2 * t]     = w1;
    g_tslot[2 * t + 1] = i2 * T_MAX + p2;  g_tw[2 * t + 1] = w2;
}

// ---------------- kernel: convert+pack W (smem-staged, coalesced) ----------
// grid (kstage=64, ntile=8, e=8), block 256
__global__ void convert_w_kernel(const float* __restrict__ W) {
    __shared__ float sbuf[B_STAGE_FLOATS];          // 32 KB
    int ks = blockIdx.x, nt = blockIdx.y, e = blockIdx.z;
    int tid = threadIdx.x;
#pragma unroll
    for (int step = 0; step < 8; step++) {
        int row = step * 32 + (tid >> 3);           // 0..255
        int ch  = tid & 7;                          // 16B chunk in 128B row
        float4 v = round4(*(const float4*)&W[
            ((size_t)e * DOUT + nt * 256 + row) * DIN + ks * BK + ch * 4]);
        sbuf[pack_idx(row, ch * 4 + 0, BN)] = v.x;
        sbuf[pack_idx(row, ch * 4 + 1, BN)] = v.y;
        sbuf[pack_idx(row, ch * 4 + 2, BN)] = v.z;
        sbuf[pack_idx(row, ch * 4 + 3, BN)] = v.w;
    }
    __syncthreads();
    float4* dst = (float4*)(g_Wp +
        (((size_t)e * 8 + nt) * 64 + ks) * B_STAGE_FLOATS);
    const float4* s4 = (const float4*)sbuf;
#pragma unroll
    for (int i = 0; i < 8; i++) dst[tid + i * 256] = s4[tid + i * 256];
}

// ---------------- kernel: gather+convert+pack X (smem-staged) ----------
// grid (kstage=64, mtile=32, e=8), block 128
__global__ void gather_x_kernel(const float* __restrict__ X) {
    __shared__ int   s_tok[BM];
    __shared__ float sbuf[A_STAGE_FLOATS];          // 16 KB
    int ks = blockIdx.x, mt = blockIdx.y, e = blockIdx.z;
    int cnt = g_cnt[e];
    int m0  = mt * BM;
    if (m0 >= cnt) return;
    int tid = threadIdx.x;
    {
        int r = m0 + tid;
        if (r >= cnt) r = cnt - 1;                  // clamp (rows unused)
        s_tok[tid] = g_tok[e * T_MAX + r];
    }
    __syncthreads();
#pragma unroll
    for (int step = 0; step < 8; step++) {
        int idx = step * 128 + tid;                 // 1024 16B chunks
        int row = idx >> 3, ch = idx & 7;
        float4 v = round4(*(const float4*)&X[
            (size_t)s_tok[row] * DIN + ks * BK + ch * 4]);
        sbuf[pack_idx(row, ch * 4 + 0, BM)] = v.x;
        sbuf[pack_idx(row, ch * 4 + 1, BM)] = v.y;
        sbuf[pack_idx(row, ch * 4 + 2, BM)] = v.z;
        sbuf[pack_idx(row, ch * 4 + 3, BM)] = v.w;
    }
    __syncthreads();
    float4* dst = (float4*)(g_Xp +
        (((size_t)e * 32 + mt) * 64 + ks) * A_STAGE_FLOATS);
    const float4* s4 = (const float4*)sbuf;
#pragma unroll
    for (int i = 0; i < 8; i++) dst[tid + i * 128] = s4[tid + i * 128];
}

// ---------------- kernel: grouped TF32 GEMM (bulk-TMA + LDS.64 frags) ----
__global__ void __launch_bounds__(256, 1)
moe_gemm_kernel() {
    int e   = blockIdx.z;
    int cnt = g_cnt[e];
    int m0  = blockIdx.y * BM;
    if (m0 >= cnt) return;
    int n0  = blockIdx.x * BN;

    extern __shared__ __align__(1024) float smem[];
    __shared__ __align__(8) uint64_t mbar_full[STAGES];
    uint32_t smem_addr = smem_u32(smem);
    uint32_t mb = smem_u32(mbar_full);

    int tid  = threadIdx.x;
    int warp = tid >> 5;
    int lane = tid & 31;
    int wm   = warp >> 2;
    int wn   = warp & 3;
    int g    = lane >> 2;
    int c    = lane & 3;

    if (tid == 0) {
#pragma unroll
        for (int s = 0; s < STAGES; s++) MBARRIER_INIT(mb + 8 * s, 1);
    }
    __syncthreads();

    const char* gA = (const char*)(g_Xp +
        ((size_t)e * 32 + blockIdx.y) * (64 * A_STAGE_FLOATS));
    const char* gB = (const char*)(g_Wp +
        ((size_t)e * 8 + blockIdx.x) * (64 * B_STAGE_FLOATS));

#define ISSUE(it)                                                             \
    do {                                                                      \
        int _s = (it) & (STAGES - 1);                                         \
        uint32_t _m = mb + 8 * _s;                                            \
        MBARRIER_EXPECT_TX(_m, STAGE_BYTES);                                  \
        bulk_ld(smem_addr + _s * STAGE_BYTES,                                 \
                gA + (size_t)(it) * A_STAGE_BYTES, A_STAGE_BYTES, _m);        \
        bulk_ld(smem_addr + _s * STAGE_BYTES + A_STAGE_BYTES,                 \
                gB + (size_t)(it) * B_STAGE_BYTES, B_STAGE_BYTES, _m);        \
    } while (0)

    if (tid == 0) { ISSUE(0); ISSUE(1); ISSUE(2); }

    float acc[4][8][4];
#pragma unroll
    for (int i = 0; i < 4; i++)
#pragma unroll
        for (int j = 0; j < 8; j++)
#pragma unroll
            for (int k = 0; k < 4; k++) acc[i][j][k] = 0.0f;

    int arow0 = wm * 64 + g;
    int brow0 = wn * 64 + g;

    // precompute per-fragment float2 offsets (slice 0); + s*BM*4 / s*BN*4
    int aoffL[4], aoffH[4], boff[8];
#pragma unroll
    for (int mt = 0; mt < 4; mt++) {
        int r0 = arow0 + mt * 16;
        int sw0 = (r0 >> 2) & 3;
        aoffL[mt] = r0 * 4 + (c ^ sw0);
        int r1 = r0 + 8;
        aoffH[mt] = r1 * 4 + (c ^ sw0 ^ 2);     // ((r0+8)>>2)&3 == sw0^2
    }
#pragma unroll
    for (int nt = 0; nt < 8; nt++) {
        int n = brow0 + nt * 8;
        int swn = (n >> 2) & 3;
        boff[nt] = n * 4 + (c ^ swn);
    }

#define COMPUTE_STAGE(st)                                                     \
    do {                                                                      \
        const float2* _sa = (const float2*)(smem + (st) * STAGE_FLOATS);      \
        const float2* _sb = (const float2*)(smem + (st) * STAGE_FLOATS        \
                                            + A_STAGE_FLOATS);               \
        _Pragma("unroll")                                                     \
        for (int s = 0; s < 4; s++) {                                         \
            unsigned af[4][4];                                                \
            _Pragma("unroll")                                                 \
            for (int mt = 0; mt < 4; mt++) {                                  \
                float2 lo = _sa[s * (BM * 4) + aoffL[mt]];                    \
                float2 hi = _sa[s * (BM * 4) + aoffH[mt]];                    \
                af[mt][0] = __float_as_uint(lo.x);                            \
                af[mt][1] = __float_as_uint(hi.x);                            \
                af[mt][2] = __float_as_uint(lo.y);                            \
                af[mt][3] = __float_as_uint(hi.y);                            \
            }                                                                 \
            _Pragma("unroll")                                                 \
            for (int nt = 0; nt < 8; nt++) {                                  \
                float2 bb = _sb[s * (BN * 4) + boff[nt]];                     \
                unsigned b0 = __float_as_uint(bb.x);                          \
                unsigned b1 = __float_as_uint(bb.y);                          \
                _Pragma("unroll")                                             \
                for (int mt = 0; mt < 4; mt++) {                              \
                    asm volatile(                                             \
                        "mma.sync.aligned.m16n8k8.row.col.f32.tf32.tf32.f32 " \
                        "{%0,%1,%2,%3}, {%4,%5,%6,%7}, {%8,%9}, "             \
                        "{%0,%1,%2,%3};\n"                                    \
                        : "+f"(acc[mt][nt][0]), "+f"(acc[mt][nt][1]),         \
                          "+f"(acc[mt][nt][2]), "+f"(acc[mt][nt][3])          \
                        : "r"(af[mt][0]), "r"(af[mt][1]),                     \
                          "r"(af[mt][2]), "r"(af[mt][3]),                     \
                          "r"(b0), "r"(b1));                                  \
                }                                                             \
            }                                                                 \
        }                                                                     \
    } while (0)

    for (int it = 0; it < KITERS; ++it) {
        int s = it & (STAGES - 1);
        MBARRIER_WAIT_PARITY(mb + 8 * s, (it >> 2) & 1);
        if (tid == 0 && it + 3 < KITERS) ISSUE(it + 3);
        COMPUTE_STAGE(s);
        __syncthreads();
    }

    // ---- epilogue: plain STG.64 into g_Y slot rows ----
    size_t ybase = ((size_t)e * T_MAX + m0) * DOUT + n0;
#pragma unroll
    for (int mt = 0; mt < 4; mt++) {
        int r0 = arow0 + mt * 16;
#pragma unroll
        for (int nt = 0; nt < 8; nt++) {
            int col = wn * 64 + nt * 8 + 2 * c;
            float2 lo = make_float2(acc[mt][nt][0], acc[mt][nt][1]);
            float2 hi = make_float2(acc[mt][nt][2], acc[mt][nt][3]);
            *(float2*)&g_Y[ybase + (size_t)r0 * DOUT + col]       = lo;
            *(float2*)&g_Y[ybase + (size_t)(r0 + 8) * DOUT + col] = hi;
        }
    }
#undef ISSUE
#undef COMPUTE_STAGE
}

// ---------------- kernel: combine two expert slots + bias -> out -------------
__global__ void combine_kernel(const float* __restrict__ Bias,
                               float* __restrict__ Out) {
    int t = blockIdx.x;
    int s1 = g_tslot[2 * t], s2 = g_tslot[2 * t + 1];
    float w1 = g_tw[2 * t],  w2 = g_tw[2 * t + 1];
    int e1 = s1 >> 12, e2 = s2 >> 12;          // T_MAX = 4096
    const float4* y1 = (const float4*)(g_Y + (size_t)s1 * DOUT);
    const float4* y2 = (const float4*)(g_Y + (size_t)s2 * DOUT);
    const float4* b1 = (const float4*)(Bias + (size_t)e1 * DOUT);
    const float4* b2 = (const float4*)(Bias + (size_t)e2 * DOUT);
    float4* o = (float4*)(Out + (size_t)t * DOUT);
    for (int j = threadIdx.x; j < DOUT / 4; j += blockDim.x) {
        float4 a = y1[j], b = b1[j], cc = y2[j], d = b2[j], r;
        r.x = w1 * (a.x + b.x) + w2 * (cc.x + d.x);
        r.y = w1 * (a.y + b.y) + w2 * (cc.y + d.y);
        r.z = w1 * (a.z + b.z) + w2 * (cc.z + d.z);
        r.w = w1 * (a.w + b.w) + w2 * (cc.w + d.w);
        o[j] = r;
    }
}

// ---------------- launcher ----------------
extern "C" void kernel_launch(void* const* d_in, const int* in_sizes, int n_in,
                              void* d_out, int out_size) {
    const float* X      = (const float*)d_in[0];
    const float* logits = (const float*)d_in[1];
    const float* W      = (const float*)d_in[2];
    const float* B      = (const float*)d_in[3];
    float* Out          = (float*)d_out;
    int T = in_sizes[1] / E_NUM;               // 4096

    static int smem_set = 0;
    if (!smem_set) {
        cudaFuncSetAttribute(moe_gemm_kernel,
                             cudaFuncAttributeMaxDynamicSharedMemorySize,
                             SMEM_DYN_BYTES);
        smem_set = 1;
    }

    zero_cnt_kernel<<<1, 32>>>();
    router_kernel<<<(T + 255) / 256, 256>>>(logits, T);
    convert_w_kernel<<<dim3(64, 8, 8), 256>>>(W);
    gather_x_kernel<<<dim3(64, 32, 8), 128>>>(X);

    dim3 grid(DOUT / BN, T_MAX / BM, E_NUM);
    moe_gemm_kernel<<<grid, 256, SMEM_DYN_BYTES>>>();

    combine_kernel<<<T, 256>>>(B, Out);
}

// round 7
// speedup vs baseline: 1.0005x; 1.0005x over previous
#include <cuda_runtime.h>
#include <cstdint>
#include <cstddef>

// ---------------- problem constants ----------------
#define E_NUM 8
#define T_MAX 4096
#define DIN   2048
#define DOUT  2048

// GEMM tiling: CTA 128x256, 8 warps (2 M x 4 N), warp tile 64x64, BK=32
#define BM 128
#define BN 256
#define BK 32
#define STAGES 4
#define KITERS (DIN / BK)     // 64

#define A_STAGE_FLOATS (BM * BK)           // 4096  (16 KB)
#define B_STAGE_FLOATS (BN * BK)           // 8192  (32 KB)
#define STAGE_FLOATS   (A_STAGE_FLOATS + B_STAGE_FLOATS)   // 12288
#define A_STAGE_BYTES  (A_STAGE_FLOATS * 4)                // 16384
#define B_STAGE_BYTES  (B_STAGE_FLOATS * 4)                // 32768
#define STAGE_BYTES    (STAGE_FLOATS * 4)                  // 49152
#define SMEM_DYN_BYTES (STAGES * STAGE_BYTES)              // 196608

// ---------------- device scratch ----------------
// Packed, tf32-rounded, smem-image operands.
// Pair-interleaved layout within a kstage block (rowsz = BM or BN):
//   float index = ((slice*rowsz + row)*4 + ((k&3) ^ sw))*2 + ((k>>2)&1)
//   slice = k>>3, sw = (row>>2)&3      (k local to the 32-k stage)
// One float2 slot holds the MMA k-pair (k=c, k=c+4)  -> LDS.64 fragments.
__device__ float g_Wp[(size_t)E_NUM * DOUT * DIN];
__device__ float g_Xp[(size_t)E_NUM * T_MAX * DIN];
__device__ float g_Y[(size_t)E_NUM * T_MAX * DOUT];
__device__ int   g_cnt[E_NUM];
__device__ int   g_tok[E_NUM * T_MAX];
__device__ int   g_tslot[T_MAX * 2];
__device__ float g_tw[T_MAX * 2];

// ---------------- helpers ----------------
__device__ __forceinline__ uint32_t smem_u32(const void* p) {
    uint32_t a;
    asm("{ .reg .u64 t; cvta.to.shared.u64 t, %1; cvt.u32.u64 %0, t; }"
        : "=r"(a) : "l"(p));
    return a;
}
__device__ __forceinline__ unsigned f2tf32(float f) {
    unsigned u;
    asm("cvt.rna.tf32.f32 %0, %1;" : "=r"(u) : "f"(f));
    return u;
}
__device__ __forceinline__ float4 round4(float4 v) {
    v.x = __uint_as_float(f2tf32(v.x));
    v.y = __uint_as_float(f2tf32(v.y));
    v.z = __uint_as_float(f2tf32(v.z));
    v.w = __uint_as_float(f2tf32(v.w));
    return v;
}
// float index inside one kstage block for element (row, k_local)
__device__ __forceinline__ uint32_t pack_idx(int row, int kl, int rowsz) {
    int slice = kl >> 3;
    int sw    = (row >> 2) & 3;
    return (uint32_t)(((slice * rowsz + row) * 4 + ((kl & 3) ^ sw)) * 2 +
                      ((kl >> 2) & 1));
}

#define MBARRIER_INIT(addr, cnt) \
    asm volatile("mbarrier.init.shared.b64 [%0], %1;" :: "r"(addr), "r"(cnt) : "memory")
#define MBARRIER_EXPECT_TX(addr, tx) \
    asm volatile("mbarrier.arrive.expect_tx.shared.b64 _, [%0], %1;" \
                 :: "r"(addr), "r"(tx) : "memory")
#define MBARRIER_WAIT_PARITY(addr, ph) do {                                   \
    uint32_t _m = (addr); uint32_t _p = (ph); uint32_t _d;                    \
    asm volatile("{\n\t.reg .pred p;\n\t"                                     \
        "mbarrier.try_wait.parity.acquire.cta.shared::cta.b64 p, [%1], %2;\n\t"\
        "selp.b32 %0, 1, 0, p;\n\t}"                                          \
        : "=r"(_d) : "r"(_m), "r"(_p) : "memory");                            \
    if (!_d) {                                                                \
        asm volatile("{\n\t.reg .pred P1;\n\t"                                \
            "WL_%=:\n\t"                                                      \
            "mbarrier.try_wait.parity.acquire.cta.shared::cta.b64 P1, [%0], %1, 0x989680;\n\t" \
            "@P1 bra.uni WD_%=;\n\t"                                          \
            "bra.uni WL_%=;\n\t"                                              \
            "WD_%=:\n\t}" :: "r"(_m), "r"(_p) : "memory");                    \
    }                                                                         \
} while (0)

__device__ __forceinline__ void bulk_ld(uint32_t sdst, const void* gsrc,
                                        uint32_t bytes, uint32_t mbar) {
    asm volatile(
        "cp.async.bulk.shared::cluster.global.mbarrier::complete_tx::bytes "
        "[%0], [%1], %2, [%3];"
        :: "r"(sdst), "l"(gsrc), "r"(bytes), "r"(mbar) : "memory");
}

// ---------------- kernel: zero counters ----------------
__global__ void zero_cnt_kernel() {
    if (threadIdx.x < E_NUM) g_cnt[threadIdx.x] = 0;
}

// ---------------- kernel: router ----------------
__global__ void router_kernel(const float* __restrict__ logits, int T) {
    int t = blockIdx.x * blockDim.x + threadIdx.x;
    if (t >= T) return;
    float l[E_NUM];
#pragma unroll
    for (int e = 0; e < E_NUM; e++) l[e] = logits[t * E_NUM + e];
    int i1 = 0; float v1 = l[0];
#pragma unroll
    for (int e = 1; e < E_NUM; e++)
        if (l[e] > v1) { v1 = l[e]; i1 = e; }
    int i2 = -1; float v2 = -3.4e38f;
#pragma unroll
    for (int e = 0; e < E_NUM; e++)
        if (e != i1 && l[e] > v2) { v2 = l[e]; i2 = e; }
    float w1 = 1.0f / (1.0f + expf(v2 - v1));
    float w2 = 1.0f - w1;
    int p1 = atomicAdd(&g_cnt[i1], 1);
    g_tok[i1 * T_MAX + p1] = t;
    int p2 = atomicAdd(&g_cnt[i2], 1);
    g_tok[i2 * T_MAX + p2] = t;
    g_tslot[2 * t]     = i1 * T_MAX + p1;  g_tw[2 * t]     = w1;
    g_tslot[2 * t + 1] = i2 * T_MAX + p2;  g_tw[2 * t + 1] = w2;
}

// ---------------- kernel: convert+pack W (smem-staged, coalesced) ----------
// grid (kstage=64, ntile=8, e=8), block 256
__global__ void convert_w_kernel(const float* __restrict__ W) {
    __shared__ float sbuf[B_STAGE_FLOATS];          // 32 KB
    int ks = blockIdx.x, nt = blockIdx.y, e = blockIdx.z;
    int tid = threadIdx.x;
#pragma unroll
    for (int step = 0; step < 8; step++) {
        int row = step * 32 + (tid >> 3);           // 0..255
        int ch  = tid & 7;                          // 16B chunk in 128B row
        float4 v = round4(*(const float4*)&W[
            ((size_t)e * DOUT + nt * 256 + row) * DIN + ks * BK + ch * 4]);
        sbuf[pack_idx(row, ch * 4 + 0, BN)] = v.x;
        sbuf[pack_idx(row, ch * 4 + 1, BN)] = v.y;
        sbuf[pack_idx(row, ch * 4 + 2, BN)] = v.z;
        sbuf[pack_idx(row, ch * 4 + 3, BN)] = v.w;
    }
    __syncthreads();
    float4* dst = (float4*)(g_Wp +
        (((size_t)e * 8 + nt) * 64 + ks) * B_STAGE_FLOATS);
    const float4* s4 = (const float4*)sbuf;
#pragma unroll
    for (int i = 0; i < 8; i++) dst[tid + i * 256] = s4[tid + i * 256];
}

// ---------------- kernel: gather+convert+pack X (smem-staged) ----------
// grid (kstage=64, mtile=32, e=8), block 128
__global__ void gather_x_kernel(const float* __restrict__ X) {
    __shared__ int   s_tok[BM];
    __shared__ float sbuf[A_STAGE_FLOATS];          // 16 KB
    int ks = blockIdx.x, mt = blockIdx.y, e = blockIdx.z;
    int cnt = g_cnt[e];
    int m0  = mt * BM;
    if (m0 >= cnt) return;
    int tid = threadIdx.x;
    {
        int r = m0 + tid;
        if (r >= cnt) r = cnt - 1;                  // clamp (rows unused)
        s_tok[tid] = g_tok[e * T_MAX + r];
    }
    __syncthreads();
#pragma unroll
    for (int step = 0; step < 8; step++) {
        int idx = step * 128 + tid;                 // 1024 16B chunks
        int row = idx >> 3, ch = idx & 7;
        float4 v = round4(*(const float4*)&X[
            (size_t)s_tok[row] * DIN + ks * BK + ch * 4]);
        sbuf[pack_idx(row, ch * 4 + 0, BM)] = v.x;
        sbuf[pack_idx(row, ch * 4 + 1, BM)] = v.y;
        sbuf[pack_idx(row, ch * 4 + 2, BM)] = v.z;
        sbuf[pack_idx(row, ch * 4 + 3, BM)] = v.w;
    }
    __syncthreads();
    float4* dst = (float4*)(g_Xp +
        (((size_t)e * 32 + mt) * 64 + ks) * A_STAGE_FLOATS);
    const float4* s4 = (const float4*)sbuf;
#pragma unroll
    for (int i = 0; i < 8; i++) dst[tid + i * 128] = s4[tid + i * 128];
}

// ---------------- kernel: grouped TF32 GEMM (bulk-TMA + LDS.64 frags) ----
__global__ void __launch_bounds__(256, 1)
moe_gemm_kernel() {
    int e   = blockIdx.z;
    int cnt = g_cnt[e];
    int m0  = blockIdx.y * BM;
    if (m0 >= cnt) return;
    int n0  = blockIdx.x * BN;

    extern __shared__ __align__(1024) float smem[];
    __shared__ __align__(8) uint64_t mbar_full[STAGES];
    uint32_t smem_addr = smem_u32(smem);
    uint32_t mb = smem_u32(mbar_full);

    int tid  = threadIdx.x;
    int warp = tid >> 5;
    int lane = tid & 31;
    int wm   = warp >> 2;
    int wn   = warp & 3;
    int g    = lane >> 2;
    int c    = lane & 3;

    if (tid == 0) {
#pragma unroll
        for (int s = 0; s < STAGES; s++) MBARRIER_INIT(mb + 8 * s, 1);
    }
    __syncthreads();

    const char* gA = (const char*)(g_Xp +
        ((size_t)e * 32 + blockIdx.y) * (64 * A_STAGE_FLOATS));
    const char* gB = (const char*)(g_Wp +
        ((size_t)e * 8 + blockIdx.x) * (64 * B_STAGE_FLOATS));

#define ISSUE(it)                                                             \
    do {                                                                      \
        int _s = (it) & (STAGES - 1);                                         \
        uint32_t _m = mb + 8 * _s;                                            \
        MBARRIER_EXPECT_TX(_m, STAGE_BYTES);                                  \
        bulk_ld(smem_addr + _s * STAGE_BYTES,                                 \
                gA + (size_t)(it) * A_STAGE_BYTES, A_STAGE_BYTES, _m);        \
        bulk_ld(smem_addr + _s * STAGE_BYTES + A_STAGE_BYTES,                 \
                gB + (size_t)(it) * B_STAGE_BYTES, B_STAGE_BYTES, _m);        \
    } while (0)

    if (tid == 0) { ISSUE(0); ISSUE(1); ISSUE(2); }

    float acc[4][8][4];
#pragma unroll
    for (int i = 0; i < 4; i++)
#pragma unroll
        for (int j = 0; j < 8; j++)
#pragma unroll
            for (int k = 0; k < 4; k++) acc[i][j][k] = 0.0f;

    int arow0 = wm * 64 + g;
    int brow0 = wn * 64 + g;

    // precompute per-fragment float2 offsets (slice 0); + s*BM*4 / s*BN*4
    int aoffL[4], aoffH[4], boff[8];
#pragma unroll
    for (int mt = 0; mt < 4; mt++) {
        int r0 = arow0 + mt * 16;
        int sw0 = (r0 >> 2) & 3;
        aoffL[mt] = r0 * 4 + (c ^ sw0);
        int r1 = r0 + 8;
        aoffH[mt] = r1 * 4 + (c ^ sw0 ^ 2);     // ((r0+8)>>2)&3 == sw0^2
    }
#pragma unroll
    for (int nt = 0; nt < 8; nt++) {
        int n = brow0 + nt * 8;
        int swn = (n >> 2) & 3;
        boff[nt] = n * 4 + (c ^ swn);
    }

#define COMPUTE_STAGE(st)                                                     \
    do {                                                                      \
        const float2* _sa = (const float2*)(smem + (st) * STAGE_FLOATS);      \
        const float2* _sb = (const float2*)(smem + (st) * STAGE_FLOATS        \
                                            + A_STAGE_FLOATS);               \
        _Pragma("unroll")                                                     \
        for (int s = 0; s < 4; s++) {                                         \
            unsigned af[4][4];                                                \
            _Pragma("unroll")                                                 \
            for (int mt = 0; mt < 4; mt++) {                                  \
                float2 lo = _sa[s * (BM * 4) + aoffL[mt]];                    \
                float2 hi = _sa[s * (BM * 4) + aoffH[mt]];                    \
                af[mt][0] = __float_as_uint(lo.x);                            \
                af[mt][1] = __float_as_uint(hi.x);                            \
                af[mt][2] = __float_as_uint(lo.y);                            \
                af[mt][3] = __float_as_uint(hi.y);                            \
            }                                                                 \
            _Pragma("unroll")                                                 \
            for (int nt = 0; nt < 8; nt++) {                                  \
                float2 bb = _sb[s * (BN * 4) + boff[nt]];                     \
                unsigned b0 = __float_as_uint(bb.x);                          \
                unsigned b1 = __float_as_uint(bb.y);                          \
                _Pragma("unroll")                                             \
                for (int mt = 0; mt < 4; mt++) {                              \
                    asm volatile(                                             \
                        "mma.sync.aligned.m16n8k8.row.col.f32.tf32.tf32.f32 " \
                        "{%0,%1,%2,%3}, {%4,%5,%6,%7}, {%8,%9}, "             \
                        "{%0,%1,%2,%3};\n"                                    \
                        : "+f"(acc[mt][nt][0]), "+f"(acc[mt][nt][1]),         \
                          "+f"(acc[mt][nt][2]), "+f"(acc[mt][nt][3])          \
                        : "r"(af[mt][0]), "r"(af[mt][1]),                     \
                          "r"(af[mt][2]), "r"(af[mt][3]),                     \
                          "r"(b0), "r"(b1));                                  \
                }                                                             \
            }                                                                 \
        }                                                                     \
    } while (0)

    for (int it = 0; it < KITERS; ++it) {
        int s = it & (STAGES - 1);
        MBARRIER_WAIT_PARITY(mb + 8 * s, (it >> 2) & 1);
        if (tid == 0 && it + 3 < KITERS) ISSUE(it + 3);
        COMPUTE_STAGE(s);
        __syncthreads();
    }

    // ---- epilogue: plain STG.64 into g_Y slot rows ----
    size_t ybase = ((size_t)e * T_MAX + m0) * DOUT + n0;
#pragma unroll
    for (int mt = 0; mt < 4; mt++) {
        int r0 = arow0 + mt * 16;
#pragma unroll
        for (int nt = 0; nt < 8; nt++) {
            int col = wn * 64 + nt * 8 + 2 * c;
            float2 lo = make_float2(acc[mt][nt][0], acc[mt][nt][1]);
            float2 hi = make_float2(acc[mt][nt][2], acc[mt][nt][3]);
            *(float2*)&g_Y[ybase + (size_t)r0 * DOUT + col]       = lo;
            *(float2*)&g_Y[ybase + (size_t)(r0 + 8) * DOUT + col] = hi;
        }
    }
#undef ISSUE
#undef COMPUTE_STAGE
}

// ---------------- kernel: combine two expert slots + bias -> out -------------
__global__ void combine_kernel(const float* __restrict__ Bias,
                               float* __restrict__ Out) {
    int t = blockIdx.x;
    int s1 = g_tslot[2 * t], s2 = g_tslot[2 * t + 1];
    float w1 = g_tw[2 * t],  w2 = g_tw[2 * t + 1];
    int e1 = s1 >> 12, e2 = s2 >> 12;          // T_MAX = 4096
    const float4* y1 = (const float4*)(g_Y + (size_t)s1 * DOUT);
    const float4* y2 = (const float4*)(g_Y + (size_t)s2 * DOUT);
    const float4* b1 = (const float4*)(Bias + (size_t)e1 * DOUT);
    const float4* b2 = (const float4*)(Bias + (size_t)e2 * DOUT);
    float4* o = (float4*)(Out + (size_t)t * DOUT);
    for (int j = threadIdx.x; j < DOUT / 4; j += blockDim.x) {
        float4 a = y1[j], b = b1[j], cc = y2[j], d = b2[j], r;
        r.x = w1 * (a.x + b.x) + w2 * (cc.x + d.x);
        r.y = w1 * (a.y + b.y) + w2 * (cc.y + d.y);
        r.z = w1 * (a.z + b.z) + w2 * (cc.z + d.z);
        r.w = w1 * (a.w + b.w) + w2 * (cc.w + d.w);
        o[j] = r;
    }
}

// ---------------- launcher ----------------
extern "C" void kernel_launch(void* const* d_in, const int* in_sizes, int n_in,
                              void* d_out, int out_size) {
    const float* X      = (const float*)d_in[0];
    const float* logits = (const float*)d_in[1];
    const float* W      = (const float*)d_in[2];
    const float* B      = (const float*)d_in[3];
    float* Out          = (float*)d_out;
    int T = in_sizes[1] / E_NUM;               // 4096

    static int smem_set = 0;
    if (!smem_set) {
        cudaFuncSetAttribute(moe_gemm_kernel,
                             cudaFuncAttributeMaxDynamicSharedMemorySize,
                             SMEM_DYN_BYTES);
        smem_set = 1;
    }

    zero_cnt_kernel<<<1, 32>>>();
    router_kernel<<<(T + 255) / 256, 256>>>(logits, T);
    convert_w_kernel<<<dim3(64, 8, 8), 256>>>(W);
    gather_x_kernel<<<dim3(64, 32, 8), 128>>>(X);

    dim3 grid(DOUT / BN, T_MAX / BM, E_NUM);
    moe_gemm_kernel<<<grid, 256, SMEM_DYN_BYTES>>>();

    combine_kernel<<<T, 256>>>(B, Out);
}